// round 16
// baseline (speedup 1.0000x reference)
#include <cuda_runtime.h>
#include <cuda_bf16.h>
#include <cuda_fp16.h>
#include <cstdint>

#define BATCH   4096
#define DIM     256
#define NROWS   8192
#define NT      64              // 64x64 grid of 128x128 tiles
#define NPAIRS  2080            // NT*(NT+1)/2 upper-triangle pairs
#define NCTAS   (2 * NPAIRS)    // 4160: two 128x64 half-tiles per pair
#define KSTEPS  8               // K=256 / k32
#define RS8     272             // smem row stride bytes (256 + 16 pad)
#define ATILE8  (128 * RS8)     // 34816 B  (A: 128 rows)
#define BTILE8  (64 * RS8)      // 17408 B  (B: 64 rows)
// logits = dot/T = acc/(16*16)*2 ; ex2 arg = acc * 2*log2(e)/256
#define EXC     0.011271055006945026f
// natural-log logit from scaled e4m3 dot: logit = acc / 128
#define PSC     0.0078125f

// Scratch (no allocations allowed)
__device__ uint8_t g_Z8[NROWS * DIM];           // normalized rows * 16, e4m3
__device__ float g_scratch[NT * NT * 256];
__device__ float g_blocksum[1024];
__device__ unsigned int g_cnt;                  // zero-init; reset by last block
__device__ int g_flag[NT];                      // block-row ready flags (reset)

__device__ __forceinline__ uint32_t smem_u32(const void* p) {
    uint32_t a;
    asm("{ .reg .u64 t; cvta.to.shared.u64 t, %1; cvt.u32.u64 %0, t; }"
        : "=r"(a) : "l"(p));
    return a;
}
#define CP16(dst, src) \
    asm volatile("cp.async.cg.shared.global [%0], [%1], 16;" \
                 :: "r"(dst), "l"(src) : "memory")
#define CP_COMMIT() asm volatile("cp.async.commit_group;" ::: "memory")
#define CP_WAIT(n)  asm volatile("cp.async.wait_group %0;" :: "n"(n) : "memory")

#define LDSM_X4(r0, r1, r2, r3, a)                                         \
    asm volatile("ldmatrix.sync.aligned.m8n8.x4.shared.b16 "               \
                 "{%0,%1,%2,%3}, [%4];"                                    \
                 : "=r"(r0), "=r"(r1), "=r"(r2), "=r"(r3) : "r"(a))

#define MMA_FP8(c, a, b0, b1)                                              \
    asm volatile("mma.sync.aligned.m16n8k32.row.col.f32.e4m3.e4m3.f32 "    \
                 "{%0,%1,%2,%3}, {%4,%5,%6,%7}, {%8,%9}, {%0,%1,%2,%3};"   \
                 : "+f"((c)[0]), "+f"((c)[1]), "+f"((c)[2]), "+f"((c)[3])  \
                 : "r"((a)[0]), "r"((a)[1]), "r"((a)[2]), "r"((a)[3]),     \
                   "r"(b0), "r"(b1))

__device__ __forceinline__ uint32_t pack_e4m3x4(float x0, float x1,
                                                float x2, float x3) {
    uint32_t w;
    asm("{ .reg .b16 s0, s1;\n\t"
        "cvt.rn.satfinite.e4m3x2.f32 s0, %2, %1;\n\t"
        "cvt.rn.satfinite.e4m3x2.f32 s1, %4, %3;\n\t"
        "mov.b32 %0, {s0, s1}; }"
        : "=r"(w) : "f"(x0), "f"(x1), "f"(x2), "f"(x3));
    return w;
}
__device__ __forceinline__ float4 unpack_e4m3x4(uint32_t w) {
    uint32_t h0, h1;
    asm("{ .reg .b16 a, b;\n\t"
        "mov.b32 {a, b}, %2;\n\t"
        "cvt.rn.f16x2.e4m3x2 %0, a;\n\t"
        "cvt.rn.f16x2.e4m3x2 %1, b; }"
        : "=r"(h0), "=r"(h1) : "r"(w));
    __half2 v0 = *reinterpret_cast<__half2*>(&h0);
    __half2 v1 = *reinterpret_cast<__half2*>(&h1);
    float2 f0 = __half22float2(v0), f1 = __half22float2(v1);
    return make_float4(f0.x, f0.y, f1.x, f1.y);
}

// ---------------------------------------------------------------------------
// Kernel A: fused symmetric e4m3 GEMM on 128x64 half-tiles + in-kernel norm.
// CTAs 0..63 first L2-normalize block-row bid (128 rows fp32 -> e4m3*16) and
// set g_flag[bid]. Every CTA spin-waits on flag[I] and flag[J] before its
// cp.async. All 64 producer CTAs are wave-1 resident (592 slots); flags are
// monotonic -> no deadlock. 128 threads, warp tile 32x64, occ=4/SM.
// ---------------------------------------------------------------------------
__global__ void __launch_bounds__(128, 4) ntx_gemm_kernel(
        const float* __restrict__ zi, const float* __restrict__ zj) {
    extern __shared__ char smem[];
    uint32_t sb = smem_u32(smem);
    float* colpart = reinterpret_cast<float*>(smem);    // [4][64]
    const uint32_t Aoff = sb + 1024;
    const uint32_t Boff = Aoff + ATILE8;

    const int p = blockIdx.x >> 1, h = blockIdx.x & 1;
    int I = (int)((129.0f - sqrtf(129.0f * 129.0f - 8.0f * (float)p)) * 0.5f);
    if (I > 63) I = 63;
    if (I < 0) I = 0;
    while (64 * (I + 1) - ((I + 1) * I) / 2 <= p) ++I;
    while (64 * I - (I * (I - 1)) / 2 > p) --I;
    const int J = I + (p - (64 * I - (I * (I - 1)) / 2));
    const bool diag = (I == J);

    const int tid = threadIdx.x, wid = tid >> 5, lane = tid & 31;

    // ---- producer phase: CTA b (< 64) normalizes block-row b ----
    if (blockIdx.x < NT) {
        const int b = blockIdx.x;
        #pragma unroll 4
        for (int it = 0; it < 32; it++) {          // warp handles one row/iter
            int row = b * 128 + it * 4 + wid;
            const float* src = (row < BATCH)
                ? (zi + (size_t)row * DIM)
                : (zj + (size_t)(row - BATCH) * DIM);
            float4 a = reinterpret_cast<const float4*>(src)[lane * 2];
            float4 bb = reinterpret_cast<const float4*>(src)[lane * 2 + 1];
            float ss = a.x*a.x + a.y*a.y + a.z*a.z + a.w*a.w
                     + bb.x*bb.x + bb.y*bb.y + bb.z*bb.z + bb.w*bb.w;
            #pragma unroll
            for (int m = 16; m >= 1; m >>= 1)
                ss += __shfl_xor_sync(0xffffffffu, ss, m);
            float s16 = rsqrtf(ss) * 16.0f;
            uint2 q;
            q.x = pack_e4m3x4(a.x*s16,  a.y*s16,  a.z*s16,  a.w*s16);
            q.y = pack_e4m3x4(bb.x*s16, bb.y*s16, bb.z*s16, bb.w*s16);
            reinterpret_cast<uint2*>(g_Z8 + (size_t)row * DIM)[lane] = q;
        }
        __syncthreads();
        __threadfence();
        if (tid == 0) atomicExch(&g_flag[b], 1);
    }

    // ---- wait for the two block-rows this tile needs ----
    if (tid == 0) {
        volatile int* f = g_flag;
        while (f[I] == 0) {}
        while (f[J] == 0) {}
    }
    __syncthreads();

    {
        const char* ga = reinterpret_cast<const char*>(g_Z8)
                       + (size_t)I * 128 * DIM;
        #pragma unroll
        for (int i = 0; i < 16; i++) {
            int idx = tid + i * 128, r = idx >> 4, c = idx & 15;
            CP16(Aoff + r * RS8 + c * 16, ga + r * DIM + c * 16);
        }
        const char* gb = reinterpret_cast<const char*>(g_Z8)
                       + (size_t)(J * 128 + h * 64) * DIM;
        #pragma unroll
        for (int i = 0; i < 8; i++) {
            int idx = tid + i * 128, r = idx >> 4, c = idx & 15;
            CP16(Boff + r * RS8 + c * 16, gb + r * DIM + c * 16);
        }
    }
    CP_COMMIT();
    CP_WAIT(0);
    __syncthreads();

    const uint32_t Arow = Aoff + (uint32_t)((wid * 32 + (lane & 7)
                        + 8 * ((lane >> 3) & 1)) * RS8 + 16 * (lane >> 4));
    const uint32_t Brow = Boff + (uint32_t)(((lane & 7)
                        + 8 * (lane >> 4)) * RS8 + 16 * ((lane >> 3) & 1));

    float acc[2][8][4];
    #pragma unroll
    for (int mt = 0; mt < 2; mt++)
        #pragma unroll
        for (int nt = 0; nt < 8; nt++)
            #pragma unroll
            for (int c = 0; c < 4; c++) acc[mt][nt][c] = 0.f;

    #pragma unroll
    for (int ks = 0; ks < KSTEPS; ks++) {
        uint32_t a[2][4], b[4][4];
        #pragma unroll
        for (int mt = 0; mt < 2; mt++)
            LDSM_X4(a[mt][0], a[mt][1], a[mt][2], a[mt][3],
                    Arow + mt * 16 * RS8 + ks * 32);
        #pragma unroll
        for (int q = 0; q < 4; q++)
            LDSM_X4(b[q][0], b[q][1], b[q][2], b[q][3],
                    Brow + q * 16 * RS8 + ks * 32);
        #pragma unroll
        for (int mt = 0; mt < 2; mt++)
            #pragma unroll
            for (int q = 0; q < 4; q++) {
                MMA_FP8(acc[mt][2 * q],     a[mt], b[q][0], b[q][1]);
                MMA_FP8(acc[mt][2 * q + 1], a[mt], b[q][2], b[q][3]);
            }
    }

    // exp in place. fragment (mt,nt,c): row = wid*32+mt*16+g(+8 for c>=2),
    // col = nt*8 + 2q + (c&1); g = lane>>2, q = lane&3.
    #pragma unroll
    for (int mt = 0; mt < 2; mt++)
        #pragma unroll
        for (int nt = 0; nt < 8; nt++)
            #pragma unroll
            for (int c = 0; c < 4; c++)
                asm("ex2.approx.f32 %0, %1;" : "+f"(acc[mt][nt][c])
                    : "f"(acc[mt][nt][c] * EXC));

    // row sums -> scratch[(I,J)][h*128 + row]
    float* rslot = g_scratch + (size_t)(I * NT + J) * 256 + h * 128;
    #pragma unroll
    for (int mt = 0; mt < 2; mt++) {
        float s0 = 0.f, s1 = 0.f;
        #pragma unroll
        for (int nt = 0; nt < 8; nt++) {
            s0 += acc[mt][nt][0] + acc[mt][nt][1];
            s1 += acc[mt][nt][2] + acc[mt][nt][3];
        }
        s0 += __shfl_xor_sync(0xffffffffu, s0, 1);
        s0 += __shfl_xor_sync(0xffffffffu, s0, 2);
        s1 += __shfl_xor_sync(0xffffffffu, s1, 1);
        s1 += __shfl_xor_sync(0xffffffffu, s1, 2);
        if ((lane & 3) == 0) {
            int g = lane >> 2;
            rslot[wid * 32 + mt * 16 + g]     = s0;
            rslot[wid * 32 + mt * 16 + 8 + g] = s1;
        }
    }

    // col sums (mirror) -> scratch[(J,I)][h*64 + c]
    if (!diag) {
        #pragma unroll
        for (int nt = 0; nt < 8; nt++) {
            float c0 = acc[0][nt][0] + acc[0][nt][2]
                     + acc[1][nt][0] + acc[1][nt][2];
            float c1 = acc[0][nt][1] + acc[0][nt][3]
                     + acc[1][nt][1] + acc[1][nt][3];
            c0 += __shfl_xor_sync(0xffffffffu, c0, 4);
            c0 += __shfl_xor_sync(0xffffffffu, c0, 8);
            c0 += __shfl_xor_sync(0xffffffffu, c0, 16);
            c1 += __shfl_xor_sync(0xffffffffu, c1, 4);
            c1 += __shfl_xor_sync(0xffffffffu, c1, 8);
            c1 += __shfl_xor_sync(0xffffffffu, c1, 16);
            if (lane < 4) {
                colpart[wid * 64 + nt * 8 + 2 * lane]     = c0;
                colpart[wid * 64 + nt * 8 + 2 * lane + 1] = c1;
            }
        }
        __syncthreads();
        if (tid < 64)
            g_scratch[(size_t)(J * NT + I) * 256 + h * 64 + tid]
                = colpart[tid] + colpart[64 + tid]
                + colpart[128 + tid] + colpart[192 + tid];
    }
}

// ---------------------------------------------------------------------------
// Kernel B: per-row loss + folded final reduction (last-block pattern).
// dself AND positive from the SAME e4m3 data (diag cancels via same ex2).
// Last block also resets g_flag and g_cnt for the next graph replay.
// ---------------------------------------------------------------------------
__global__ void ntx_loss_kernel(float* __restrict__ out) {
    int wid = threadIdx.x >> 5, lid = threadIdx.x & 31;
    int row = blockIdx.x * 8 + wid;
    int pos = (row < BATCH) ? row + BATCH : row - BATCH;
    int Ib = row >> 7, r = row & 127;

    float rsum = 0.f;
    #pragma unroll
    for (int s = 0; s < 2; s++) {
        int Jb = lid + s * 32;
        const float* slot = g_scratch + (size_t)(Ib * NT + Jb) * 256;
        rsum += slot[r];
        if (Jb >= Ib) rsum += slot[128 + r];
    }

    uint2 qr = reinterpret_cast<const uint2*>(g_Z8 + (size_t)row * DIM)[lid];
    uint2 qp = reinterpret_cast<const uint2*>(g_Z8 + (size_t)pos * DIM)[lid];
    float4 r0 = unpack_e4m3x4(qr.x), r1 = unpack_e4m3x4(qr.y);
    float4 p0 = unpack_e4m3x4(qp.x), p1 = unpack_e4m3x4(qp.y);
    float dself = r0.x*r0.x + r0.y*r0.y + r0.z*r0.z + r0.w*r0.w
                + r1.x*r1.x + r1.y*r1.y + r1.z*r1.z + r1.w*r1.w;
    float dpos  = r0.x*p0.x + r0.y*p0.y + r0.z*p0.z + r0.w*p0.w
                + r1.x*p1.x + r1.y*p1.y + r1.z*p1.z + r1.w*p1.w;

    #pragma unroll
    for (int m = 16; m >= 1; m >>= 1) {
        rsum  += __shfl_xor_sync(0xffffffffu, rsum,  m);
        dself += __shfl_xor_sync(0xffffffffu, dself, m);
        dpos  += __shfl_xor_sync(0xffffffffu, dpos,  m);
    }
    __shared__ float ls[8];
    __shared__ int is_last;
    if (lid == 0) {
        float diagterm;
        asm("ex2.approx.f32 %0, %1;" : "=f"(diagterm) : "f"(dself * EXC));
        ls[wid] = logf(rsum - diagterm) - dpos * PSC;
    }
    __syncthreads();
    if (threadIdx.x == 0) {
        float s = 0.f;
        #pragma unroll
        for (int i = 0; i < 8; i++) s += ls[i];
        g_blocksum[blockIdx.x] = s;
        __threadfence();
        unsigned int done = atomicAdd(&g_cnt, 1u);
        is_last = (done == gridDim.x - 1) ? 1 : 0;
    }
    __syncthreads();

    if (is_last) {                       // deterministic fixed-order sum
        __shared__ float sm[256];
        int t = threadIdx.x;
        sm[t] = g_blocksum[t] + g_blocksum[t + 256]
              + g_blocksum[t + 512] + g_blocksum[t + 768];
        __syncthreads();
        for (int w = 128; w >= 1; w >>= 1) {
            if (t < w) sm[t] += sm[t + w];
            __syncthreads();
        }
        if (t < NT) g_flag[t] = 0;       // reset flags for next replay
        if (t == 0) {
            out[0] = sm[0] / (float)NROWS;
            g_cnt = 0;                   // reset for next graph replay
        }
    }
}

// ---------------------------------------------------------------------------
extern "C" void kernel_launch(void* const* d_in, const int* in_sizes, int n_in,
                              void* d_out, int out_size) {
    const float* zi = (const float*)d_in[0];
    const float* zj = (const float*)d_in[1];
    float* out = (float*)d_out;

    const int smem_bytes = 1024 + ATILE8 + BTILE8;   // 53248 -> 4 CTAs/SM
    cudaFuncSetAttribute(ntx_gemm_kernel,
                         cudaFuncAttributeMaxDynamicSharedMemorySize, smem_bytes);

    ntx_gemm_kernel<<<NCTAS, 128, smem_bytes>>>(zi, zj);
    ntx_loss_kernel<<<1024, 256>>>(out);
}

// round 17
// speedup vs baseline: 1.1006x; 1.1006x over previous
#include <cuda_runtime.h>
#include <cuda_bf16.h>
#include <cuda_fp16.h>
#include <cstdint>

#define BATCH   4096
#define DIM     256
#define NROWS   8192
#define NT      64              // 64x64 grid of 128x128 tiles
#define NPAIRS  2080            // NT*(NT+1)/2 upper-triangle pairs
#define NCTAS   (2 * NPAIRS)    // 4160: two 128x64 half-tiles per pair
#define KSTEPS  8               // K=256 / k32
#define RS8     272             // smem row stride bytes (256 + 16 pad)
#define ATILE8  (128 * RS8)     // 34816 B  (A: 128 rows)
#define BTILE8  (64 * RS8)      // 17408 B  (B: 64 rows)
// logits = dot/T = acc/(16*16)*2 ; ex2 arg = acc * 2*log2(e)/256
#define EXC     0.011271055006945026f
// natural-log logit from scaled e4m3 dot: logit = acc / 128
#define PSC     0.0078125f

// Scratch (no allocations allowed)
__device__ uint8_t g_Z8[NROWS * DIM];           // normalized rows * 16, e4m3
// [Ib*NT+Jb][256]: computed pairs (Ib<=Jb): h*128+r partial rowsums (sum both)
// mirror slots (Ib>Jb): [0..127] complete rowsums from colsum path
__device__ float g_scratch[NT * NT * 256];
__device__ float g_blocksum[1024];
__device__ unsigned int g_cnt;                  // zero-init; reset by last block

__device__ __forceinline__ uint32_t smem_u32(const void* p) {
    uint32_t a;
    asm("{ .reg .u64 t; cvta.to.shared.u64 t, %1; cvt.u32.u64 %0, t; }"
        : "=r"(a) : "l"(p));
    return a;
}
#define CP16(dst, src) \
    asm volatile("cp.async.cg.shared.global [%0], [%1], 16;" \
                 :: "r"(dst), "l"(src) : "memory")
#define CP_COMMIT() asm volatile("cp.async.commit_group;" ::: "memory")
#define CP_WAIT(n)  asm volatile("cp.async.wait_group %0;" :: "n"(n) : "memory")

#define LDSM_X4(r0, r1, r2, r3, a)                                         \
    asm volatile("ldmatrix.sync.aligned.m8n8.x4.shared.b16 "               \
                 "{%0,%1,%2,%3}, [%4];"                                    \
                 : "=r"(r0), "=r"(r1), "=r"(r2), "=r"(r3) : "r"(a))

#define MMA_FP8(c, a, b0, b1)                                              \
    asm volatile("mma.sync.aligned.m16n8k32.row.col.f32.e4m3.e4m3.f32 "    \
                 "{%0,%1,%2,%3}, {%4,%5,%6,%7}, {%8,%9}, {%0,%1,%2,%3};"   \
                 : "+f"((c)[0]), "+f"((c)[1]), "+f"((c)[2]), "+f"((c)[3])  \
                 : "r"((a)[0]), "r"((a)[1]), "r"((a)[2]), "r"((a)[3]),     \
                   "r"(b0), "r"(b1))

__device__ __forceinline__ uint32_t pack_e4m3x4(float x0, float x1,
                                                float x2, float x3) {
    uint32_t w;
    asm("{ .reg .b16 s0, s1;\n\t"
        "cvt.rn.satfinite.e4m3x2.f32 s0, %2, %1;\n\t"
        "cvt.rn.satfinite.e4m3x2.f32 s1, %4, %3;\n\t"
        "mov.b32 %0, {s0, s1}; }"
        : "=r"(w) : "f"(x0), "f"(x1), "f"(x2), "f"(x3));
    return w;
}
__device__ __forceinline__ float4 unpack_e4m3x4(uint32_t w) {
    uint32_t h0, h1;
    asm("{ .reg .b16 a, b;\n\t"
        "mov.b32 {a, b}, %2;\n\t"
        "cvt.rn.f16x2.e4m3x2 %0, a;\n\t"
        "cvt.rn.f16x2.e4m3x2 %1, b; }"
        : "=r"(h0), "=r"(h1) : "r"(w));
    __half2 v0 = *reinterpret_cast<__half2*>(&h0);
    __half2 v1 = *reinterpret_cast<__half2*>(&h1);
    float2 f0 = __half22float2(v0), f1 = __half22float2(v1);
    return make_float4(f0.x, f0.y, f1.x, f1.y);
}

// ---------------------------------------------------------------------------
// Kernel 1: L2-normalize rows -> e4m3*16 (GEMM path only). Warp per row.
// ---------------------------------------------------------------------------
__global__ void ntx_norm_kernel(const float* __restrict__ zi,
                                const float* __restrict__ zj) {
    int wid = threadIdx.x >> 5, lid = threadIdx.x & 31;
    int row = blockIdx.x * 8 + wid;
    const float* src = (row < BATCH) ? (zi + (size_t)row * DIM)
                                     : (zj + (size_t)(row - BATCH) * DIM);
    float4 a = reinterpret_cast<const float4*>(src)[lid * 2];
    float4 b = reinterpret_cast<const float4*>(src)[lid * 2 + 1];
    float ss = a.x*a.x + a.y*a.y + a.z*a.z + a.w*a.w
             + b.x*b.x + b.y*b.y + b.z*b.z + b.w*b.w;
    #pragma unroll
    for (int m = 16; m >= 1; m >>= 1) ss += __shfl_xor_sync(0xffffffffu, ss, m);
    float s16 = rsqrtf(ss) * 16.0f;

    uint2 q;
    q.x = pack_e4m3x4(a.x*s16, a.y*s16, a.z*s16, a.w*s16);
    q.y = pack_e4m3x4(b.x*s16, b.y*s16, b.z*s16, b.w*s16);
    reinterpret_cast<uint2*>(g_Z8 + (size_t)row * DIM)[lid] = q;
}

// ---------------------------------------------------------------------------
// Kernel 2: symmetric e4m3 GEMM on 128x64 half-tiles.
// CTA c: pair p = c>>1 -> (I,J) upper triangle, half h = c&1.
// 128 threads, 4 warps, warp tile 32x64. occ=4/SM; HW wave scheduling.
// ---------------------------------------------------------------------------
__global__ void __launch_bounds__(128, 4) ntx_gemm_kernel() {
    extern __shared__ char smem[];
    uint32_t sb = smem_u32(smem);
    float* colpart = reinterpret_cast<float*>(smem);    // [4][64]
    const uint32_t Aoff = sb + 1024;
    const uint32_t Boff = Aoff + ATILE8;

    const int p = blockIdx.x >> 1, h = blockIdx.x & 1;
    int I = (int)((129.0f - sqrtf(129.0f * 129.0f - 8.0f * (float)p)) * 0.5f);
    if (I > 63) I = 63;
    if (I < 0) I = 0;
    while (64 * (I + 1) - ((I + 1) * I) / 2 <= p) ++I;
    while (64 * I - (I * (I - 1)) / 2 > p) --I;
    const int J = I + (p - (64 * I - (I * (I - 1)) / 2));
    const bool diag = (I == J);

    const int tid = threadIdx.x, wid = tid >> 5, lane = tid & 31;

    {
        const char* ga = reinterpret_cast<const char*>(g_Z8)
                       + (size_t)I * 128 * DIM;
        #pragma unroll
        for (int i = 0; i < 16; i++) {
            int idx = tid + i * 128, r = idx >> 4, c = idx & 15;
            CP16(Aoff + r * RS8 + c * 16, ga + r * DIM + c * 16);
        }
        const char* gb = reinterpret_cast<const char*>(g_Z8)
                       + (size_t)(J * 128 + h * 64) * DIM;
        #pragma unroll
        for (int i = 0; i < 8; i++) {
            int idx = tid + i * 128, r = idx >> 4, c = idx & 15;
            CP16(Boff + r * RS8 + c * 16, gb + r * DIM + c * 16);
        }
    }
    CP_COMMIT();
    CP_WAIT(0);
    __syncthreads();

    const uint32_t Arow = Aoff + (uint32_t)((wid * 32 + (lane & 7)
                        + 8 * ((lane >> 3) & 1)) * RS8 + 16 * (lane >> 4));
    const uint32_t Brow = Boff + (uint32_t)(((lane & 7)
                        + 8 * (lane >> 4)) * RS8 + 16 * ((lane >> 3) & 1));

    float acc[2][8][4];
    #pragma unroll
    for (int mt = 0; mt < 2; mt++)
        #pragma unroll
        for (int nt = 0; nt < 8; nt++)
            #pragma unroll
            for (int c = 0; c < 4; c++) acc[mt][nt][c] = 0.f;

    #pragma unroll
    for (int ks = 0; ks < KSTEPS; ks++) {
        uint32_t a[2][4], b[4][4];
        #pragma unroll
        for (int mt = 0; mt < 2; mt++)
            LDSM_X4(a[mt][0], a[mt][1], a[mt][2], a[mt][3],
                    Arow + mt * 16 * RS8 + ks * 32);
        #pragma unroll
        for (int q = 0; q < 4; q++)
            LDSM_X4(b[q][0], b[q][1], b[q][2], b[q][3],
                    Brow + q * 16 * RS8 + ks * 32);
        #pragma unroll
        for (int mt = 0; mt < 2; mt++)
            #pragma unroll
            for (int q = 0; q < 4; q++) {
                MMA_FP8(acc[mt][2 * q],     a[mt], b[q][0], b[q][1]);
                MMA_FP8(acc[mt][2 * q + 1], a[mt], b[q][2], b[q][3]);
            }
    }

    // exp in place. fragment (mt,nt,c): row = wid*32+mt*16+g(+8 for c>=2),
    // col = nt*8 + 2q + (c&1); g = lane>>2, q = lane&3.
    #pragma unroll
    for (int mt = 0; mt < 2; mt++)
        #pragma unroll
        for (int nt = 0; nt < 8; nt++)
            #pragma unroll
            for (int c = 0; c < 4; c++)
                asm("ex2.approx.f32 %0, %1;" : "+f"(acc[mt][nt][c])
                    : "f"(acc[mt][nt][c] * EXC));

    // row sums -> scratch[(I,J)][h*128 + row]
    float* rslot = g_scratch + (size_t)(I * NT + J) * 256 + h * 128;
    #pragma unroll
    for (int mt = 0; mt < 2; mt++) {
        float s0 = 0.f, s1 = 0.f;
        #pragma unroll
        for (int nt = 0; nt < 8; nt++) {
            s0 += acc[mt][nt][0] + acc[mt][nt][1];
            s1 += acc[mt][nt][2] + acc[mt][nt][3];
        }
        s0 += __shfl_xor_sync(0xffffffffu, s0, 1);
        s0 += __shfl_xor_sync(0xffffffffu, s0, 2);
        s1 += __shfl_xor_sync(0xffffffffu, s1, 1);
        s1 += __shfl_xor_sync(0xffffffffu, s1, 2);
        if ((lane & 3) == 0) {
            int g = lane >> 2;
            rslot[wid * 32 + mt * 16 + g]     = s0;
            rslot[wid * 32 + mt * 16 + 8 + g] = s1;
        }
    }

    // col sums (mirror) -> scratch[(J,I)][h*64 + c]
    if (!diag) {
        #pragma unroll
        for (int nt = 0; nt < 8; nt++) {
            float c0 = acc[0][nt][0] + acc[0][nt][2]
                     + acc[1][nt][0] + acc[1][nt][2];
            float c1 = acc[0][nt][1] + acc[0][nt][3]
                     + acc[1][nt][1] + acc[1][nt][3];
            c0 += __shfl_xor_sync(0xffffffffu, c0, 4);
            c0 += __shfl_xor_sync(0xffffffffu, c0, 8);
            c0 += __shfl_xor_sync(0xffffffffu, c0, 16);
            c1 += __shfl_xor_sync(0xffffffffu, c1, 4);
            c1 += __shfl_xor_sync(0xffffffffu, c1, 8);
            c1 += __shfl_xor_sync(0xffffffffu, c1, 16);
            if (lane < 4) {
                colpart[wid * 64 + nt * 8 + 2 * lane]     = c0;
                colpart[wid * 64 + nt * 8 + 2 * lane + 1] = c1;
            }
        }
        __syncthreads();
        if (tid < 64)
            g_scratch[(size_t)(J * NT + I) * 256 + h * 64 + tid]
                = colpart[tid] + colpart[64 + tid]
                + colpart[128 + tid] + colpart[192 + tid];
    }
}

// ---------------------------------------------------------------------------
// Kernel 3: per-row loss + folded final reduction (last-block pattern).
// dself AND positive from the SAME e4m3 data (diag cancels via same ex2).
// ---------------------------------------------------------------------------
__global__ void ntx_loss_kernel(float* __restrict__ out) {
    int wid = threadIdx.x >> 5, lid = threadIdx.x & 31;
    int row = blockIdx.x * 8 + wid;
    int pos = (row < BATCH) ? row + BATCH : row - BATCH;
    int Ib = row >> 7, r = row & 127;

    float rsum = 0.f;
    #pragma unroll
    for (int s = 0; s < 2; s++) {
        int Jb = lid + s * 32;
        const float* slot = g_scratch + (size_t)(Ib * NT + Jb) * 256;
        rsum += slot[r];
        if (Jb >= Ib) rsum += slot[128 + r];
    }

    uint2 qr = reinterpret_cast<const uint2*>(g_Z8 + (size_t)row * DIM)[lid];
    uint2 qp = reinterpret_cast<const uint2*>(g_Z8 + (size_t)pos * DIM)[lid];
    float4 r0 = unpack_e4m3x4(qr.x), r1 = unpack_e4m3x4(qr.y);
    float4 p0 = unpack_e4m3x4(qp.x), p1 = unpack_e4m3x4(qp.y);
    float dself = r0.x*r0.x + r0.y*r0.y + r0.z*r0.z + r0.w*r0.w
                + r1.x*r1.x + r1.y*r1.y + r1.z*r1.z + r1.w*r1.w;
    float dpos  = r0.x*p0.x + r0.y*p0.y + r0.z*p0.z + r0.w*p0.w
                + r1.x*p1.x + r1.y*p1.y + r1.z*p1.z + r1.w*p1.w;

    #pragma unroll
    for (int m = 16; m >= 1; m >>= 1) {
        rsum  += __shfl_xor_sync(0xffffffffu, rsum,  m);
        dself += __shfl_xor_sync(0xffffffffu, dself, m);
        dpos  += __shfl_xor_sync(0xffffffffu, dpos,  m);
    }
    __shared__ float ls[8];
    __shared__ int is_last;
    if (lid == 0) {
        float diagterm;
        asm("ex2.approx.f32 %0, %1;" : "=f"(diagterm) : "f"(dself * EXC));
        ls[wid] = logf(rsum - diagterm) - dpos * PSC;
    }
    __syncthreads();
    if (threadIdx.x == 0) {
        float s = 0.f;
        #pragma unroll
        for (int i = 0; i < 8; i++) s += ls[i];
        g_blocksum[blockIdx.x] = s;
        __threadfence();
        unsigned int done = atomicAdd(&g_cnt, 1u);
        is_last = (done == gridDim.x - 1) ? 1 : 0;
    }
    __syncthreads();

    if (is_last) {                       // deterministic fixed-order sum
        __shared__ float sm[256];
        int t = threadIdx.x;
        sm[t] = g_blocksum[t] + g_blocksum[t + 256]
              + g_blocksum[t + 512] + g_blocksum[t + 768];
        __syncthreads();
        for (int w = 128; w >= 1; w >>= 1) {
            if (t < w) sm[t] += sm[t + w];
            __syncthreads();
        }
        if (t == 0) {
            out[0] = sm[0] / (float)NROWS;
            g_cnt = 0;                   // reset for next graph replay
        }
    }
}

// ---------------------------------------------------------------------------
extern "C" void kernel_launch(void* const* d_in, const int* in_sizes, int n_in,
                              void* d_out, int out_size) {
    const float* zi = (const float*)d_in[0];
    const float* zj = (const float*)d_in[1];
    float* out = (float*)d_out;

    const int smem_bytes = 1024 + ATILE8 + BTILE8;   // 53248 -> 4 CTAs/SM
    cudaFuncSetAttribute(ntx_gemm_kernel,
                         cudaFuncAttributeMaxDynamicSharedMemorySize, smem_bytes);

    ntx_norm_kernel<<<1024, 256>>>(zi, zj);
    ntx_gemm_kernel<<<NCTAS, 128, smem_bytes>>>();
    ntx_loss_kernel<<<1024, 256>>>(out);
}